// round 1
// baseline (speedup 1.0000x reference)
#include <cuda_runtime.h>
#include <cuda_bf16.h>
#include <cstdint>

// DistortionLoss:
//   bins   = (z - near) / (far - near)                  (N+1 per row)
//   m_i    = 0.5*(bins_i + bins_{i+1})                  (N per row, sorted)
//   loss   = sum_{i,j} w_i w_j |m_i - m_j|
//          + (1/3) * sum_i w_i^2 (bins_{i+1} - bins_i)
// Sorted-midpoint identity:
//   sum_{i,j} w_i w_j |m_i - m_j| = 2 * sum_i w_i * (m_i * W_i^< - S_i^<)
// with W_i^< = sum_{j<i} w_j, S_i^< = sum_{j<i} w_j m_j.  -> O(N) per row.
//
// One warp per row, 4 elements per lane. R=8192, N=128.

#define FULL 0xffffffffu

__global__ __launch_bounds__(256, 8)
void distortion_loss_kernel(const float* __restrict__ w,
                            const float* __restrict__ z,
                            const float* __restrict__ nearv,
                            const float* __restrict__ farv,
                            float* __restrict__ out,
                            int R)
{
    const int gwarp = (blockIdx.x * blockDim.x + threadIdx.x) >> 5;
    const int lane  = threadIdx.x & 31;
    if (gwarp >= R) return;

    const float* wr = w + (size_t)gwarp * 128;
    const float* zr = z + (size_t)gwarp * 129;

    const float nr  = __ldg(&nearv[gwarp]);
    const float fr  = __ldg(&farv[gwarp]);
    const float inv = 1.0f / (fr - nr);

    // ---- loads (fully coalesced) ----
    // weights: row stride 128 floats -> 16B aligned, use float4
    const float4 w4 = reinterpret_cast<const float4*>(wr)[lane];
    float wv[4] = {w4.x, w4.y, w4.z, w4.w};

    // z: row stride 129 floats (not 16B aligned) -> scalar loads
    const int zi = lane * 4;
    float z0 = __ldg(&zr[zi + 0]);
    float z1 = __ldg(&zr[zi + 1]);
    float z2 = __ldg(&zr[zi + 2]);
    float z3 = __ldg(&zr[zi + 3]);
    // z4 = next lane's z0; lane 31 loads the row's final element z[128]
    float z4 = __shfl_down_sync(FULL, z0, 1);
    if (lane == 31) z4 = __ldg(&zr[128]);

    // normalized bins
    const float b0 = (z0 - nr) * inv;
    const float b1 = (z1 - nr) * inv;
    const float b2 = (z2 - nr) * inv;
    const float b3 = (z3 - nr) * inv;
    const float b4 = (z4 - nr) * inv;

    float m[4]  = {0.5f*(b0+b1), 0.5f*(b1+b2), 0.5f*(b2+b3), 0.5f*(b3+b4)};
    float dz[4] = {b1-b0, b2-b1, b3-b2, b4-b3};

    // ---- in-lane serial exclusive scan + local pair accumulation ----
    float wc = 0.0f;   // lane-local cumulative sum of w            (W within lane)
    float sc = 0.0f;   // lane-local cumulative sum of w*m          (S within lane)
    float pairAcc = 0.0f;
    float intra   = 0.0f;
#pragma unroll
    for (int i = 0; i < 4; ++i) {
        pairAcc += wv[i] * (m[i] * wc - sc);   // j < i, same lane
        wc += wv[i];
        sc  = fmaf(wv[i], m[i], sc);
        intra = fmaf(wv[i]*wv[i], dz[i], intra);
    }

    // ---- warp exclusive scan of lane totals (wc, sc) ----
    float wInc = wc, sInc = sc;
#pragma unroll
    for (int o = 1; o < 32; o <<= 1) {
        float tw = __shfl_up_sync(FULL, wInc, o);
        float ts = __shfl_up_sync(FULL, sInc, o);
        if (lane >= o) { wInc += tw; sInc += ts; }
    }
    const float Wex = wInc - wc;   // sum over all earlier lanes
    const float Sex = sInc - sc;

    // cross-lane pairs: sum_i wv[i]*(m[i]*Wex - Sex) = Wex*sc - Sex*wc
    pairAcc += Wex * sc - Sex * wc;

    // ---- warp reduction ----
    float loss = 2.0f * pairAcc + (1.0f / 3.0f) * intra;
#pragma unroll
    for (int o = 16; o > 0; o >>= 1)
        loss += __shfl_xor_sync(FULL, loss, o);

    if (lane == 0) out[gwarp] = loss;
}

extern "C" void kernel_launch(void* const* d_in, const int* in_sizes, int n_in,
                              void* d_out, int out_size)
{
    const float* w  = (const float*)d_in[0];   // (R, 128, 1)
    const float* z  = (const float*)d_in[1];   // (R, 129)
    const float* nr = (const float*)d_in[2];   // (R, 1)
    const float* fr = (const float*)d_in[3];   // (R, 1)
    float* out = (float*)d_out;                // (R, 1)

    const int R = in_sizes[0] / 128;
    const int threads = 256;                    // 8 warps = 8 rows per block
    const int blocks  = (R * 32 + threads - 1) / threads;
    distortion_loss_kernel<<<blocks, threads>>>(w, z, nr, fr, out, R);
}

// round 2
// speedup vs baseline: 1.0462x; 1.0462x over previous
#include <cuda_runtime.h>
#include <cuda_bf16.h>
#include <cstdint>

// DistortionLoss, O(N) per row via gap decomposition:
//   bins = (z - near)/(far - near); m_i = 0.5*(bins_i + bins_{i+1}) (sorted)
//   sum_{i,j} w_i w_j |m_i - m_j| = 2 * sum_{e=1..N-1} d_e * P_e * (T - P_e)
//     d_e = m_e - m_{e-1},  P_e = sum_{i<e} w_i (exclusive prefix), T = sum w
//   + (1/3) * sum_i w_i^2 (bins_{i+1} - bins_i)
//
// One warp handles TWO rows (independent chains for ILP); 4 elems/lane/row.

#define FULL 0xffffffffu

__global__ __launch_bounds__(128)
void distortion_loss_kernel(const float* __restrict__ w,
                            const float* __restrict__ z,
                            const float* __restrict__ nearv,
                            const float* __restrict__ farv,
                            float* __restrict__ out,
                            int R)
{
    const int warp = (blockIdx.x * blockDim.x + threadIdx.x) >> 5;
    const int lane = threadIdx.x & 31;
    const int row0 = warp * 2;
    if (row0 >= R) return;

    float loss[2];

#pragma unroll
    for (int r = 0; r < 2; ++r) {
        const int row = row0 + r;
        const float* wr = w + (size_t)row * 128;
        const float* zr = z + (size_t)row * 129;

        const float nr  = __ldg(&nearv[row]);
        const float fr  = __ldg(&farv[row]);
        const float inv = __fdividef(1.0f, fr - nr);

        // ---- loads (fully coalesced) ----
        const float4 w4 = reinterpret_cast<const float4*>(wr)[lane];

        const int zi = lane * 4;
        float z0 = __ldg(&zr[zi + 0]);
        float z1 = __ldg(&zr[zi + 1]);
        float z2 = __ldg(&zr[zi + 2]);
        float z3 = __ldg(&zr[zi + 3]);
        float z4 = __shfl_down_sync(FULL, z0, 1);     // next lane's first z
        if (lane == 31) z4 = __ldg(&zr[128]);

        // normalized bins + midpoints + widths
        const float b0 = (z0 - nr) * inv;
        const float b1 = (z1 - nr) * inv;
        const float b2 = (z2 - nr) * inv;
        const float b3 = (z3 - nr) * inv;
        const float b4 = (z4 - nr) * inv;

        const float m0 = 0.5f * (b0 + b1);
        const float m1 = 0.5f * (b1 + b2);
        const float m2 = 0.5f * (b2 + b3);
        const float m3 = 0.5f * (b3 + b4);

        // ---- single warp scan (inclusive) of per-lane w totals ----
        const float pre1 = w4.x;
        const float pre2 = pre1 + w4.y;
        const float pre3 = pre2 + w4.z;
        const float wc   = pre3 + w4.w;     // lane-local total

        float wInc = wc;
#pragma unroll
        for (int o = 1; o < 32; o <<= 1) {
            float t = __shfl_up_sync(FULL, wInc, o);
            if (lane >= o) wInc += t;
        }
        const float Wex = wInc - wc;                       // exclusive lane prefix
        const float T   = __shfl_sync(FULL, wInc, 31);     // row total

        // previous lane's last midpoint (lane 0: P=0 kills the term)
        const float mPrev = __shfl_up_sync(FULL, m3, 1);

        // ---- gap accumulation: sum d_e * P_e * (T - P_e) ----
        const float P0 = Wex;
        const float P1 = Wex + pre1;
        const float P2 = Wex + pre2;
        const float P3 = Wex + pre3;

        float acc;
        acc  = (m0 - mPrev) * (P0 * (T - P0));
        acc += (m1 - m0)    * (P1 * (T - P1));
        acc += (m2 - m1)    * (P2 * (T - P2));
        acc += (m3 - m2)    * (P3 * (T - P3));

        // ---- intra-bin term ----
        float intra;
        intra  = (w4.x * w4.x) * (b1 - b0);
        intra  = fmaf(w4.y * w4.y, b2 - b1, intra);
        intra  = fmaf(w4.z * w4.z, b3 - b2, intra);
        intra  = fmaf(w4.w * w4.w, b4 - b3, intra);

        loss[r] = 2.0f * acc + (1.0f / 3.0f) * intra;
    }

    // ---- butterfly reductions (both rows interleaved) ----
#pragma unroll
    for (int o = 16; o > 0; o >>= 1) {
        loss[0] += __shfl_xor_sync(FULL, loss[0], o);
        loss[1] += __shfl_xor_sync(FULL, loss[1], o);
    }

    if (lane == 0) {
        out[row0]     = loss[0];
        out[row0 + 1] = loss[1];
    }
}

extern "C" void kernel_launch(void* const* d_in, const int* in_sizes, int n_in,
                              void* d_out, int out_size)
{
    const float* w  = (const float*)d_in[0];   // (R, 128, 1)
    const float* z  = (const float*)d_in[1];   // (R, 129)
    const float* nr = (const float*)d_in[2];   // (R, 1)
    const float* fr = (const float*)d_in[3];   // (R, 1)
    float* out = (float*)d_out;                // (R, 1)

    const int R = in_sizes[0] / 128;
    const int threads = 128;                   // 4 warps -> 8 rows per block
    const int rowsPerBlock = (threads / 32) * 2;
    const int blocks = (R + rowsPerBlock - 1) / rowsPerBlock;
    distortion_loss_kernel<<<blocks, threads>>>(w, z, nr, fr, out, R);
}